// round 12
// baseline (speedup 1.0000x reference)
#include <cuda_runtime.h>
#include <stdint.h>

// BinarizedLinear: act[d,o] = sum_i W[d,o,i]*x[d,i]; out[d,o] = (act > bias[d,o]) ? 1 : 0
// D=64, OUT=2048, IN=2048.
//
// R12 (final): exact-bound skip kernel at the harness replay floor.
//   Bound: act <= count[d] = sum_i x[d,i]; count <= bias => out = 0 with no
//   weight read. Per-warp autonomous count (16 back-to-back LDG.128 over the
//   L2-hot x row + 5-shfl butterfly), zero smem/barriers. Zero-store and bias
//   load hoisted ahead of the count (independent -> overlap load latency).
//   Exact warp-cooperative fallback for any count > bias row keeps worst-case
//   inputs correct at the R2 93%-DRAM streaming rate.

#define D_DIRS 64
#define OUT_F  2048
#define IN_F   2048
#define THREADS 128                        // 4 warps, 1 output per thread... x4
#define BLOCKS_PER_D 8                     // 256 outputs per block
#define BLOCKS  (D_DIRS * BLOCKS_PER_D)    // 512 CTAs

__global__ __launch_bounds__(THREADS)
void binlin_fused(const float* __restrict__ W,
                  const float* __restrict__ x,
                  const float* __restrict__ bias,
                  float* __restrict__ out)
{
    const int d     = blockIdx.x >> 3;
    const int obase = (blockIdx.x & 7) << 8;    // 0..1792 step 256
    const int lane  = threadIdx.x & 31;

    // Each thread owns 2 consecutive outputs. Issue the (cnt-independent)
    // zero-store and bias load FIRST so they overlap the x-load latency.
    const int o0   = obase + threadIdx.x * 2;
    const int idx0 = d * OUT_F + o0;

    float2 z; z.x = z.y = 0.0f;
    ((float2*)out)[idx0 >> 1] = z;
    const float2 b2 = __ldg((const float2*)bias + (idx0 >> 1));

    // Warp-autonomous count[d]: 16 back-to-back LDG.128 per lane (L2-hot x),
    // two accumulators to halve the exposed FADD chain, 5-shfl butterfly.
    const float4* __restrict__ xr = (const float4*)x + (size_t)d * (IN_F / 4);
    float s0 = 0.0f, s1 = 0.0f;
    #pragma unroll
    for (int it = 0; it < 16; it += 2) {
        float4 v0 = __ldg(&xr[it * 32 + lane]);
        float4 v1 = __ldg(&xr[(it + 1) * 32 + lane]);
        s0 += (v0.x + v0.y) + (v0.z + v0.w);
        s1 += (v1.x + v1.y) + (v1.z + v1.w);
    }
    float s = s0 + s1;
    #pragma unroll
    for (int off = 16; off > 0; off >>= 1)
        s += __shfl_xor_sync(0xFFFFFFFFu, s, off);
    const float cnt = s;                        // identical in all lanes

    unsigned flags = 0;
    if (cnt > b2.x) flags |= 1u;
    if (cnt > b2.y) flags |= 2u;

    // Exact fallback: warp cooperatively computes any row where count > bias,
    // overwriting that row's zero (same-thread program order).
    unsigned m = __ballot_sync(0xFFFFFFFFu, flags != 0);
    while (m) {
        const int src = __ffs(m) - 1;
        m &= m - 1u;
        const unsigned f     = __shfl_sync(0xFFFFFFFFu, flags, src);
        const int      sidx0 = __shfl_sync(0xFFFFFFFFu, idx0, src);

        #pragma unroll
        for (int j = 0; j < 2; ++j) {
            if (!(f & (1u << j))) continue;
            const int row = sidx0 + j;
            const float4* __restrict__ wr =
                (const float4*)W + (size_t)row * (IN_F / 4);

            float acc = 0.0f;
            #pragma unroll
            for (int it = 0; it < 16; ++it) {
                float4 w  = __ldg(&wr[it * 32 + lane]);
                float4 xv = __ldg(&xr[it * 32 + lane]);   // L2-resident
                acc = fmaf(w.x, xv.x, acc);
                acc = fmaf(w.y, xv.y, acc);
                acc = fmaf(w.z, xv.z, acc);
                acc = fmaf(w.w, xv.w, acc);
            }
            #pragma unroll
            for (int off = 16; off > 0; off >>= 1)
                acc += __shfl_xor_sync(0xFFFFFFFFu, acc, off);

            if (lane == src) {
                const float bv = (j == 0) ? b2.x : b2.y;
                out[row] = (acc > bv) ? 1.0f : 0.0f;
            }
        }
    }
}

extern "C" void kernel_launch(void* const* d_in, const int* in_sizes, int n_in,
                              void* d_out, int out_size)
{
    const float* W    = (const float*)d_in[0];
    const float* x    = (const float*)d_in[1];
    const float* bias = (const float*)d_in[2];
    float*       out  = (float*)d_out;

    binlin_fused<<<BLOCKS, THREADS>>>(W, x, bias, out);   // 512 CTAs, 1 launch
}